// round 11
// baseline (speedup 1.0000x reference)
#include <cuda_runtime.h>
#include <cuda_bf16.h>

// Problem constants
#define B_ 8
#define S_ 1024
#define D_ 256
#define NR (B_*S_)   // 8192 rows

// Scratch (static device allocations — allowed)
__device__ float g_xq[NR*D_];          // rope(q) f32 (for mw)
__device__ float g_xv[NR*D_];          // rope(v) f32 (for mw)
// bf16x2-packed {hi,lo} pairs: uint2 per k-pair, 128 pairs per row of 256
__device__ __align__(16) uint2 g_xs [NR*128];       // X split
__device__ __align__(16) uint2 g_wqs[D_*128];       // Wq split
__device__ __align__(16) uint2 g_wvs[D_*128];       // Wv split
__device__ __align__(16) uint2 g_xqs[NR*128];       // rope(q) split
__device__ __align__(16) uint2 g_w2s[B_*D_*128];    // W2^T split [b][n][kpair]

// ---------------------------------------------------------------------------
// 3xBF16: x = hi + lo (bf16 each); C += Ah·Bh + Ah·Bl + Al·Bh (lo·lo dropped)
// ---------------------------------------------------------------------------
__device__ __forceinline__ uint2 splt2(float x0, float x1){
    unsigned hp;  // {x1_hi | x0_hi}
    asm("cvt.rn.bf16x2.f32 %0, %1, %2;" : "=r"(hp) : "f"(x1), "f"(x0));
    float h0 = __uint_as_float(hp << 16);
    float h1 = __uint_as_float(hp & 0xffff0000u);
    unsigned lp;
    asm("cvt.rn.bf16x2.f32 %0, %1, %2;" : "=r"(lp) : "f"(x1 - h1), "f"(x0 - h0));
    return make_uint2(hp, lp);
}
__device__ __forceinline__ void mma_bf16(float* d, const unsigned* a, const unsigned* b){
    asm volatile(
        "mma.sync.aligned.m16n8k16.row.col.f32.bf16.bf16.f32 "
        "{%0,%1,%2,%3}, {%4,%5,%6,%7}, {%8,%9}, {%0,%1,%2,%3};"
        : "+f"(d[0]), "+f"(d[1]), "+f"(d[2]), "+f"(d[3])
        : "r"(a[0]), "r"(a[1]), "r"(a[2]), "r"(a[3]),
          "r"(b[0]), "r"(b[1]));
}
__device__ __forceinline__ void cpa16(void* sdst, const void* gsrc){
    unsigned s = (unsigned)__cvta_generic_to_shared(sdst);
    asm volatile("cp.async.ca.shared.global [%0], [%1], 16;" :: "r"(s), "l"(gsrc));
}
#define CP_COMMIT() asm volatile("cp.async.commit_group;")
#define CP_WAIT1()  asm volatile("cp.async.wait_group 1;" ::: "memory")
#define CP_WAIT0()  asm volatile("cp.async.wait_group 0;" ::: "memory")

// ---------------------------------------------------------------------------
// K0: pre-split X, Wq, Wv into {hi,lo} bf16x2 pairs. 16 floats/thread.
// ---------------------------------------------------------------------------
__global__ __launch_bounds__(256) void presplit_kernel(
    const float* __restrict__ X,
    const float* __restrict__ Wq,
    const float* __restrict__ Wv)
{
    int bid = blockIdx.x;
    const float* src; uint2* dst; int tl;
    if (bid < 512)      { src = X;  dst = g_xs;  tl = bid*256 + threadIdx.x; }
    else if (bid < 528) { src = Wq; dst = g_wqs; tl = (bid-512)*256 + threadIdx.x; }
    else                { src = Wv; dst = g_wvs; tl = (bid-528)*256 + threadIdx.x; }
    size_t f0 = (size_t)tl * 16;
    #pragma unroll
    for (int c = 0; c < 2; c++) {
        float4 a = *(const float4*)(src + f0 + c*8);
        float4 b = *(const float4*)(src + f0 + c*8 + 4);
        uint2 p0 = splt2(a.x, a.y), p1 = splt2(a.z, a.w);
        uint2 p2 = splt2(b.x, b.y), p3 = splt2(b.z, b.w);
        *(uint4*)(dst + f0/2 + c*4)     = make_uint4(p0.x, p0.y, p1.x, p1.y);
        *(uint4*)(dst + f0/2 + c*4 + 2) = make_uint4(p2.x, p2.y, p3.x, p3.y);
    }
}

// Tile layout: uint2{hi,lo} per k-pair, [64][12] per stage (pitch 12 —
// fragment reads conflict-free per half-warp: banks {j, j+12, j+8, j+4}).
// 3-stage cp.async pipeline, 1 __syncthreads per slab, 128-thread CTAs.

// Fragment load within a stage tile (rows x 12)
#define FRAG_A(TILE)                                                          \
    _Pragma("unroll")                                                         \
    for (int mi = 0; mi < 2; mi++) {                                          \
        int r = wm*32 + mi*16 + g;                                            \
        uint2 q;                                                              \
        q = TILE[r  ][tg  ]; aH[mi][0]=q.x; aL[mi][0]=q.y;                    \
        q = TILE[r+8][tg  ]; aH[mi][1]=q.x; aL[mi][1]=q.y;                    \
        q = TILE[r  ][tg+4]; aH[mi][2]=q.x; aL[mi][2]=q.y;                    \
        q = TILE[r+8][tg+4]; aH[mi][3]=q.x; aL[mi][3]=q.y;                    \
    }
#define FRAG_B(TILE)                                                          \
    _Pragma("unroll")                                                         \
    for (int ni = 0; ni < 4; ni++) {                                          \
        int nn = wn*32 + ni*8 + g;                                            \
        uint2 q;                                                              \
        q = TILE[nn][tg  ]; bH[ni][0]=q.x; bL[ni][0]=q.y;                     \
        q = TILE[nn][tg+4]; bH[ni][1]=q.x; bL[ni][1]=q.y;                     \
    }
// Term-major MMA: RAW distance 8 between writes to the same accumulator.
#define MMA_3TERM(ACC)                                                        \
    _Pragma("unroll")                                                         \
    for (int mi = 0; mi < 2; mi++)                                            \
        _Pragma("unroll")                                                     \
        for (int ni = 0; ni < 4; ni++) mma_bf16(ACC[mi][ni], aH[mi], bH[ni]); \
    _Pragma("unroll")                                                         \
    for (int mi = 0; mi < 2; mi++)                                            \
        _Pragma("unroll")                                                     \
        for (int ni = 0; ni < 4; ni++) mma_bf16(ACC[mi][ni], aH[mi], bL[ni]); \
    _Pragma("unroll")                                                         \
    for (int mi = 0; mi < 2; mi++)                                            \
        _Pragma("unroll")                                                     \
        for (int ni = 0; ni < 4; ni++) mma_bf16(ACC[mi][ni], aL[mi], bH[ni]);

// ---------------------------------------------------------------------------
// K1: fused Q+V projection + bias + RoPE. BM=64 BN=64 BK=16, 128 threads,
// warp grid 2x2, warp tile 32x32. grid (128, 4).
// dyn smem: As[3][64][12] | Bq[3][64][12] | Bv[3][64][12] = 54 KB.
// ---------------------------------------------------------------------------
#define QV_SMEM (3*3*64*12*8)
__global__ __launch_bounds__(128, 4) void qv2_tc(
    const float* __restrict__ bq, const float* __restrict__ bv)
{
    extern __shared__ __align__(16) uint2 dyn[];
    uint2 (*As)[64][12] = (uint2(*)[64][12])(dyn);
    uint2 (*Bq)[64][12] = (uint2(*)[64][12])(dyn + 3*64*12);
    uint2 (*Bv)[64][12] = (uint2(*)[64][12])(dyn + 6*64*12);

    const int t = threadIdx.x;
    const int lane = t & 31, warp = t >> 5;
    const int g = lane >> 2, tg = lane & 3;
    const int wm = warp & 1, wn = warp >> 1;
    const int m0 = blockIdx.x * 64;
    const int nb = blockIdx.y * 64;

    float accQ[2][4][4] = {};
    float accV[2][4][4] = {};

    // store-phase indices: 2 iterations cover 64 rows x 4 chunks of 16B
    #define QV_ISSUE(s_, kt_) do {                                              \
        int kb_ = (kt_)*8;                                                      \
        _Pragma("unroll")                                                       \
        for (int i = 0; i < 2; i++) {                                           \
            int id = t + i*128;                                                 \
            int row = id >> 2, j0 = (id & 3) * 2;                               \
            cpa16(&As[s_][row][j0], g_xs  + (size_t)(m0+row)*128 + kb_ + j0);   \
            cpa16(&Bq[s_][row][j0], g_wqs + (size_t)(nb+row)*128 + kb_ + j0);   \
            cpa16(&Bv[s_][row][j0], g_wvs + (size_t)(nb+row)*128 + kb_ + j0);   \
        }                                                                       \
        CP_COMMIT();                                                            \
    } while (0)

    QV_ISSUE(0, 0);
    QV_ISSUE(1, 1);

    #pragma unroll
    for (int it = 0; it < 16; it++) {
        const int cur = it % 3;
        if (it < 15) { CP_WAIT1(); } else { CP_WAIT0(); }
        __syncthreads();
        if (it + 2 < 16) { QV_ISSUE((it+2)%3, it+2); }
        {
            unsigned aH[2][4], aL[2][4], bH[4][2], bL[4][2];
            FRAG_A(As[cur]);
            FRAG_B(Bq[cur]);
            MMA_3TERM(accQ);
            FRAG_B(Bv[cur]);
            MMA_3TERM(accV);
        }
    }
    #undef QV_ISSUE

    // Epilogue: bias + RoPE (theta uniform per block: nb-aligned halves).
    const float th = (nb < 128) ? 1.0f : 1e-4f;
    #pragma unroll
    for (int mi = 0; mi < 2; mi++) {
        #pragma unroll
        for (int half = 0; half < 2; half++) {
            int r = m0 + wm*32 + mi*16 + g + half*8;
            float pos = (float)((r & (S_-1)) + 1);     // 1-indexed position
            float sv, cv; sincosf(pos * th, &sv, &cv);
            #pragma unroll
            for (int ni = 0; ni < 4; ni++) {
                int d = nb + wn*32 + ni*8 + 2*tg;
                float xe, xo;
                xe = accQ[mi][ni][half*2+0] + bq[d];
                xo = accQ[mi][ni][half*2+1] + bq[d+1];
                float2 oq = make_float2(xe*sv - xo*cv, xe*cv + xo*sv);
                *(float2*)(g_xq + (size_t)r*D_ + d) = oq;
                g_xqs[(size_t)r*128 + d/2] = splt2(oq.x, oq.y);
                xe = accV[mi][ni][half*2+0] + bv[d];
                xo = accV[mi][ni][half*2+1] + bv[d+1];
                *(float2*)(g_xv + (size_t)r*D_ + d) = make_float2(xe*sv - xo*cv, xe*cv + xo*sv);
            }
        }
    }
}

// ---------------------------------------------------------------------------
// K2 (fused): per (b,h): M[e][f] = (1/4) * sum_s xq[..e]*xv[..f], then
// W2T[b][n][16h+e] = sum_f M[e][f]*wo[n][16h+f], stored split.
// ---------------------------------------------------------------------------
__global__ __launch_bounds__(256) void mw_kernel(const float* __restrict__ Wo)
{
    __shared__ __align__(16) char smem_raw[38912];
    float (*qs)[20]       = (float(*)[20])(smem_raw);
    float (*vs)[20]       = (float(*)[20])(smem_raw + 10240);
    float (*part)[16][17] = (float(*)[16][17])(smem_raw + 20480);
    float (*wos)[20]      = (float(*)[20])(smem_raw);            // phase2 overlay
    __shared__ float Ms[16][16];

    const int bh = blockIdx.x, b = bh >> 4, h = bh & 15;
    const float* __restrict__ q = g_xq + (size_t)b*S_*D_ + h*16;
    const float* __restrict__ v = g_xv + (size_t)b*S_*D_ + h*16;
    const int t = threadIdx.x;
    const int grp = t >> 4, lt = t & 15;
    const int e4 = (lt >> 2) * 4, f4 = (lt & 3) * 4;
    float c[4][4] = {};

    for (int chunk = 0; chunk < 8; chunk++) {
        int sb = chunk * 128;
        #pragma unroll
        for (int i = 0; i < 2; i++) {
            int idx = t + i*256;
            int row = idx >> 2, c4 = (idx & 3) * 4;
            *(float4*)&qs[row][c4] = *(const float4*)(q + (size_t)(sb+row)*D_ + c4);
            *(float4*)&vs[row][c4] = *(const float4*)(v + (size_t)(sb+row)*D_ + c4);
        }
        __syncthreads();
        int r0 = grp * 8;
        #pragma unroll
        for (int ss = 0; ss < 8; ss++) {
            float4 q4 = *(const float4*)&qs[r0+ss][e4];
            float4 v4 = *(const float4*)&vs[r0+ss][f4];
            c[0][0] += q4.x*v4.x; c[0][1] += q4.x*v4.y; c[0][2] += q4.x*v4.z; c[0][3] += q4.x*v4.w;
            c[1][0] += q4.y*v4.x; c[1][1] += q4.y*v4.y; c[1][2] += q4.y*v4.z; c[1][3] += q4.y*v4.w;
            c[2][0] += q4.z*v4.x; c[2][1] += q4.z*v4.y; c[2][2] += q4.z*v4.z; c[2][3] += q4.z*v4.w;
            c[3][0] += q4.w*v4.x; c[3][1] += q4.w*v4.y; c[3][2] += q4.w*v4.z; c[3][3] += q4.w*v4.w;
        }
        __syncthreads();
    }
    #pragma unroll
    for (int i = 0; i < 4; i++)
        #pragma unroll
        for (int j = 0; j < 4; j++)
            part[grp][e4+i][f4+j] = c[i][j];
    __syncthreads();
    {
        int e = t >> 4, f = t & 15;
        float s = 0.f;
        #pragma unroll
        for (int gg = 0; gg < 16; gg++) s += part[gg][e][f];
        __syncthreads();                 // all part reads done before wos overwrite
        Ms[e][f] = s * 0.25f;            // 1/sqrt(HD=16)
    }
    #pragma unroll
    for (int i = 0; i < 4; i++) {
        int idx = t + i*256;
        int row = idx >> 2, c4 = (idx & 3) * 4;
        *(float4*)&wos[row][c4] = *(const float4*)(Wo + (size_t)row*D_ + h*16 + c4);
    }
    __syncthreads();
    const int n = t;
    float vals[16];
    #pragma unroll
    for (int e = 0; e < 16; e++) {
        float a = 0.f;
        #pragma unroll
        for (int f = 0; f < 16; f++) a += Ms[e][f] * wos[n][f];
        vals[e] = a;
    }
    uint2* outp = g_w2s + ((size_t)b*D_ + n)*128 + h*8;   // [n][kpair]
    #pragma unroll
    for (int e = 0; e < 16; e += 2)
        outp[e/2] = splt2(vals[e], vals[e+1]);
}

// ---------------------------------------------------------------------------
// K3: out_b = xq_b @ W2T_b^T + bo. BM=64 BN=64 BK=16, 128 threads,
// warp grid 2x2. grid (4, 16, 8): x = n-block, y = m-block, z = batch.
// dyn smem: As[3][64][12] | Bs[3][64][12] = 36 KB.
// ---------------------------------------------------------------------------
#define OUT_SMEM (3*2*64*12*8)
__global__ __launch_bounds__(128, 4) void out_tc(
    const float* __restrict__ bo, float* __restrict__ out)
{
    extern __shared__ __align__(16) uint2 dyn2[];
    uint2 (*As)[64][12] = (uint2(*)[64][12])(dyn2);
    uint2 (*Bs)[64][12] = (uint2(*)[64][12])(dyn2 + 3*64*12);

    const int t = threadIdx.x;
    const int lane = t & 31, warp = t >> 5;
    const int g = lane >> 2, tg = lane & 3;
    const int wm = warp & 1, wn = warp >> 1;
    const int bz = blockIdx.z;
    const int m0 = blockIdx.y * 64, n0 = blockIdx.x * 64;
    const uint2* __restrict__ Axs = g_xqs + (size_t)bz*S_*128;
    const uint2* __restrict__ Bws = g_w2s + (size_t)bz*D_*128;

    float acc[2][4][4] = {};

    #define OUT_ISSUE(s_, kt_) do {                                             \
        int kb_ = (kt_)*8;                                                      \
        _Pragma("unroll")                                                       \
        for (int i = 0; i < 2; i++) {                                           \
            int id = t + i*128;                                                 \
            int row = id >> 2, j0 = (id & 3) * 2;                               \
            cpa16(&As[s_][row][j0], Axs + (size_t)(m0+row)*128 + kb_ + j0);     \
            cpa16(&Bs[s_][row][j0], Bws + (size_t)(n0+row)*128 + kb_ + j0);     \
        }                                                                       \
        CP_COMMIT();                                                            \
    } while (0)

    OUT_ISSUE(0, 0);
    OUT_ISSUE(1, 1);

    #pragma unroll
    for (int it = 0; it < 16; it++) {
        const int cur = it % 3;
        if (it < 15) { CP_WAIT1(); } else { CP_WAIT0(); }
        __syncthreads();
        if (it + 2 < 16) { OUT_ISSUE((it+2)%3, it+2); }
        {
            unsigned aH[2][4], aL[2][4], bH[4][2], bL[4][2];
            FRAG_A(As[cur]);
            FRAG_B(Bs[cur]);
            MMA_3TERM(acc);
        }
    }
    #undef OUT_ISSUE

    #pragma unroll
    for (int mi = 0; mi < 2; mi++) {
        #pragma unroll
        for (int half = 0; half < 2; half++) {
            int r = bz*S_ + m0 + wm*32 + mi*16 + g + half*8;
            #pragma unroll
            for (int ni = 0; ni < 4; ni++) {
                int d = n0 + wn*32 + ni*8 + 2*tg;
                float2 o = make_float2(acc[mi][ni][half*2+0] + bo[d],
                                       acc[mi][ni][half*2+1] + bo[d+1]);
                *(float2*)(out + (size_t)r*D_ + d) = o;
            }
        }
    }
}

// ---------------------------------------------------------------------------
extern "C" void kernel_launch(void* const* d_in, const int* in_sizes, int n_in,
                              void* d_out, int out_size)
{
    (void)in_sizes; (void)n_in; (void)out_size;
    const float* x   = (const float*)d_in[0];
    const float* wqw = (const float*)d_in[1];
    const float* wqb = (const float*)d_in[2];
    // d_in[3], d_in[4] = wk_w, wk_b : dead in reference
    const float* wvw = (const float*)d_in[5];
    const float* wvb = (const float*)d_in[6];
    const float* wow = (const float*)d_in[7];
    const float* wob = (const float*)d_in[8];
    float* out = (float*)d_out;

    cudaFuncSetAttribute(qv2_tc, cudaFuncAttributeMaxDynamicSharedMemorySize, QV_SMEM);
    cudaFuncSetAttribute(out_tc, cudaFuncAttributeMaxDynamicSharedMemorySize, OUT_SMEM);

    presplit_kernel<<<544, 256>>>(x, wqw, wvw);
    qv2_tc<<<dim3(128, 4), 128, QV_SMEM>>>(wqb, wvb);
    mw_kernel<<<128, 256>>>(wow);
    out_tc<<<dim3(4, 16, 8), 128, OUT_SMEM>>>(wob, out);
}

// round 12
// speedup vs baseline: 1.4741x; 1.4741x over previous
#include <cuda_runtime.h>
#include <cuda_bf16.h>

// Problem constants
#define B_ 8
#define S_ 1024
#define D_ 256
#define NR (B_*S_)   // 8192 rows

// Scratch (static device allocations — allowed)
__device__ float g_xq[NR*D_];          // rope(q) f32 (for mw)
__device__ float g_xv[NR*D_];          // rope(v) f32 (for mw)
// bf16 planes, 2 bf16 packed per unsigned; 128 unsigned per 256-wide row
__device__ __align__(16) unsigned g_xh [NR*128], g_xl [NR*128];     // X
__device__ __align__(16) unsigned g_wqh[D_*128], g_wql[D_*128];     // Wq
__device__ __align__(16) unsigned g_wvh[D_*128], g_wvl[D_*128];     // Wv
__device__ __align__(16) unsigned g_xqh[NR*128], g_xql[NR*128];     // rope(q)
__device__ __align__(16) unsigned g_w2h[B_*D_*128], g_w2l[B_*D_*128]; // W2^T [b][n][k]

// ---------------------------------------------------------------------------
// 3xBF16: x = hi + lo (bf16 each); C += Ah·Bh + Ah·Bl + Al·Bh (lo·lo dropped)
// ---------------------------------------------------------------------------
__device__ __forceinline__ uint2 splt2(float x0, float x1){
    unsigned hp;  // {x1_hi | x0_hi}
    asm("cvt.rn.bf16x2.f32 %0, %1, %2;" : "=r"(hp) : "f"(x1), "f"(x0));
    float h0 = __uint_as_float(hp << 16);
    float h1 = __uint_as_float(hp & 0xffff0000u);
    unsigned lp;
    asm("cvt.rn.bf16x2.f32 %0, %1, %2;" : "=r"(lp) : "f"(x1 - h1), "f"(x0 - h0));
    return make_uint2(hp, lp);
}
__device__ __forceinline__ void mma_bf16(float* d, const unsigned* a, const unsigned* b){
    asm volatile(
        "mma.sync.aligned.m16n8k16.row.col.f32.bf16.bf16.f32 "
        "{%0,%1,%2,%3}, {%4,%5,%6,%7}, {%8,%9}, {%0,%1,%2,%3};"
        : "+f"(d[0]), "+f"(d[1]), "+f"(d[2]), "+f"(d[3])
        : "r"(a[0]), "r"(a[1]), "r"(a[2]), "r"(a[3]),
          "r"(b[0]), "r"(b[1]));
}
__device__ __forceinline__ void ldsm4(unsigned& r0, unsigned& r1,
                                      unsigned& r2, unsigned& r3, unsigned addr){
    asm volatile("ldmatrix.sync.aligned.m8n8.x4.shared.b16 {%0,%1,%2,%3}, [%4];"
        : "=r"(r0), "=r"(r1), "=r"(r2), "=r"(r3) : "r"(addr));
}
__device__ __forceinline__ unsigned s2u(const void* p){
    return (unsigned)__cvta_generic_to_shared(p);
}
__device__ __forceinline__ void cpa16s(unsigned sdst, const void* gsrc){
    asm volatile("cp.async.ca.shared.global [%0], [%1], 16;" :: "r"(sdst), "l"(gsrc));
}
#define CP_COMMIT() asm volatile("cp.async.commit_group;")
#define CP_WAIT1()  asm volatile("cp.async.wait_group 1;" ::: "memory")
#define CP_WAIT0()  asm volatile("cp.async.wait_group 0;" ::: "memory")

// ---------------------------------------------------------------------------
// K0: pre-split X, Wq, Wv into bf16 hi/lo planes. 16 floats/thread.
// ---------------------------------------------------------------------------
__global__ __launch_bounds__(256) void presplit_kernel(
    const float* __restrict__ X,
    const float* __restrict__ Wq,
    const float* __restrict__ Wv)
{
    int bid = blockIdx.x;
    const float* src; unsigned *dh, *dl; int tl;
    if (bid < 512)      { src = X;  dh = g_xh;  dl = g_xl;  tl = bid*256 + threadIdx.x; }
    else if (bid < 528) { src = Wq; dh = g_wqh; dl = g_wql; tl = (bid-512)*256 + threadIdx.x; }
    else                { src = Wv; dh = g_wvh; dl = g_wvl; tl = (bid-528)*256 + threadIdx.x; }
    size_t f0 = (size_t)tl * 16;
    #pragma unroll
    for (int c = 0; c < 2; c++) {
        float4 a = *(const float4*)(src + f0 + c*8);
        float4 b = *(const float4*)(src + f0 + c*8 + 4);
        uint2 p0 = splt2(a.x, a.y), p1 = splt2(a.z, a.w);
        uint2 p2 = splt2(b.x, b.y), p3 = splt2(b.z, b.w);
        *(uint4*)(dh + f0/2 + c*4) = make_uint4(p0.x, p1.x, p2.x, p3.x);
        *(uint4*)(dl + f0/2 + c*4) = make_uint4(p0.y, p1.y, p2.y, p3.y);
    }
}

// ---------------------------------------------------------------------------
// Smem tile layout: per k16 slab, each plane row = 16 bf16 = 32 B at pitch 48
// (16 B pad -> every LDSM phase is a perfect 16B-bank permutation).
// 3-stage cp.async pipeline, one __syncthreads per slab.
// ---------------------------------------------------------------------------
#define RP 48
// qv stage offsets
#define QAH 0
#define QAL 6144
#define QBQH 12288
#define QBQL 15360
#define QBVH 18432
#define QBVL 21504
#define QSTG 24576
#define QV_SMEM (3*QSTG)       // 72 KB
// out stage offsets
#define OAH 0
#define OAL 6144
#define OBH 12288
#define OBL 15360
#define OSTG 18432
#define OUT_SMEM (3*OSTG)      // 54 KB

// B fragment unpack from one x4 over n16: {r0,r2} -> n0-7, {r1,r3} -> n8-15
#define LOAD_B32(DST, BASE)                                                   \
    _Pragma("unroll")                                                         \
    for (int hf = 0; hf < 2; hf++) {                                          \
        unsigned t0,t1,t2,t3;                                                 \
        ldsm4(t0,t1,t2,t3, (BASE) + (unsigned)((wn*32 + hf*16)*RP) + lofs);   \
        DST[hf*2  ][0]=t0; DST[hf*2  ][1]=t2;                                 \
        DST[hf*2+1][0]=t1; DST[hf*2+1][1]=t3;                                 \
    }
#define LOAD_A(BASEH, BASEL)                                                  \
    _Pragma("unroll")                                                         \
    for (int mi = 0; mi < 2; mi++) {                                          \
        unsigned ro = (unsigned)((wm*32 + mi*16)*RP) + lofs;                  \
        ldsm4(aH[mi][0],aH[mi][1],aH[mi][2],aH[mi][3], (BASEH) + ro);         \
        ldsm4(aL[mi][0],aL[mi][1],aL[mi][2],aL[mi][3], (BASEL) + ro);         \
    }
// Term-major MMA: RAW distance 8 between writes to same accumulator.
#define MMA_3TERM(ACC)                                                        \
    _Pragma("unroll")                                                         \
    for (int mi = 0; mi < 2; mi++)                                            \
        _Pragma("unroll")                                                     \
        for (int ni = 0; ni < 4; ni++) mma_bf16(ACC[mi][ni], aH[mi], bH[ni]); \
    _Pragma("unroll")                                                         \
    for (int mi = 0; mi < 2; mi++)                                            \
        _Pragma("unroll")                                                     \
        for (int ni = 0; ni < 4; ni++) mma_bf16(ACC[mi][ni], aH[mi], bL[ni]); \
    _Pragma("unroll")                                                         \
    for (int mi = 0; mi < 2; mi++)                                            \
        _Pragma("unroll")                                                     \
        for (int ni = 0; ni < 4; ni++) mma_bf16(ACC[mi][ni], aL[mi], bH[ni]);

// ---------------------------------------------------------------------------
// K1: fused Q+V projection + bias + RoPE. BM=128 BN=64 BK=16, 256 threads,
// 8 warps (4m x 2n), warp tile 32x32. grid (64, 4).
// ---------------------------------------------------------------------------
__global__ __launch_bounds__(256, 2) void qv2_tc(
    const float* __restrict__ bq, const float* __restrict__ bv)
{
    extern __shared__ __align__(16) char dyn[];
    const unsigned smb = s2u(dyn);
    const int t = threadIdx.x;
    const int lane = t & 31, warp = t >> 5;
    const int g = lane >> 2, tg = lane & 3;
    const int wm = warp & 3, wn = warp >> 2;
    const unsigned lofs = (unsigned)((lane & 15)*RP + (lane >> 4)*16);
    const int m0 = blockIdx.x * 128;
    const int nb = blockIdx.y * 64;

    float accQ[2][4][4] = {};
    float accV[2][4][4] = {};

    #define QV_ISSUE(s_, kt_) do {                                              \
        unsigned sb_ = smb + (s_)*QSTG;                                         \
        int kbase = (kt_)*8;                                                    \
        _Pragma("unroll")                                                       \
        for (int i = 0; i < 2; i++) {                                           \
            int id = t + i*256;                                                 \
            int row = id >> 2, rem = id & 3;                                    \
            int pl = rem >> 1, ch = rem & 1;                                    \
            const unsigned* sA = pl ? g_xl : g_xh;                              \
            cpa16s(sb_ + (unsigned)(pl*6144 + row*RP + ch*16),                  \
                   sA + (size_t)(m0+row)*128 + kbase + ch*4);                   \
        }                                                                       \
        {                                                                       \
            int row = t >> 2, rem = t & 3;                                      \
            int pl = rem >> 1, ch = rem & 1;                                    \
            const unsigned* sq = pl ? g_wql : g_wqh;                            \
            const unsigned* sv = pl ? g_wvl : g_wvh;                            \
            unsigned o_ = (unsigned)(pl*3072 + row*RP + ch*16);                 \
            cpa16s(sb_ + QBQH + o_, sq + (size_t)(nb+row)*128 + kbase + ch*4);  \
            cpa16s(sb_ + QBVH + o_, sv + (size_t)(nb+row)*128 + kbase + ch*4);  \
        }                                                                       \
        CP_COMMIT();                                                            \
    } while (0)

    QV_ISSUE(0, 0);
    QV_ISSUE(1, 1);

    #pragma unroll
    for (int it = 0; it < 16; it++) {
        const int cur = it % 3;
        if (it < 15) { CP_WAIT1(); } else { CP_WAIT0(); }
        __syncthreads();
        if (it + 2 < 16) { QV_ISSUE((it+2)%3, it+2); }
        {
            unsigned sb = smb + cur*QSTG;
            unsigned aH[2][4], aL[2][4], bH[4][2], bL[4][2];
            LOAD_A(sb + QAH, sb + QAL);
            LOAD_B32(bH, sb + QBQH);
            LOAD_B32(bL, sb + QBQL);
            MMA_3TERM(accQ);
            LOAD_B32(bH, sb + QBVH);
            LOAD_B32(bL, sb + QBVL);
            MMA_3TERM(accV);
        }
    }
    #undef QV_ISSUE

    // Epilogue: bias + RoPE (theta uniform per block: nb-aligned halves).
    const float th = (nb < 128) ? 1.0f : 1e-4f;
    #pragma unroll
    for (int mi = 0; mi < 2; mi++) {
        #pragma unroll
        for (int half = 0; half < 2; half++) {
            int r = m0 + wm*32 + mi*16 + g + half*8;
            float pos = (float)((r & (S_-1)) + 1);     // 1-indexed position
            float sv, cv; sincosf(pos * th, &sv, &cv);
            #pragma unroll
            for (int ni = 0; ni < 4; ni++) {
                int d = nb + wn*32 + ni*8 + 2*tg;
                float xe, xo;
                xe = accQ[mi][ni][half*2+0] + bq[d];
                xo = accQ[mi][ni][half*2+1] + bq[d+1];
                float2 oq = make_float2(xe*sv - xo*cv, xe*cv + xo*sv);
                *(float2*)(g_xq + (size_t)r*D_ + d) = oq;
                uint2 pr = splt2(oq.x, oq.y);
                g_xqh[(size_t)r*128 + d/2] = pr.x;
                g_xql[(size_t)r*128 + d/2] = pr.y;
                xe = accV[mi][ni][half*2+0] + bv[d];
                xo = accV[mi][ni][half*2+1] + bv[d+1];
                *(float2*)(g_xv + (size_t)r*D_ + d) = make_float2(xe*sv - xo*cv, xe*cv + xo*sv);
            }
        }
    }
}

// ---------------------------------------------------------------------------
// K2 (fused): per (b,h): M[e][f] = (1/4) * sum_s xq[..e]*xv[..f], then
// W2T[b][n][16h+e] = sum_f M[e][f]*wo[n][16h+f], stored as bf16 planes.
// ---------------------------------------------------------------------------
__global__ __launch_bounds__(256) void mw_kernel(const float* __restrict__ Wo)
{
    __shared__ __align__(16) char smem_raw[38912];
    float (*qs)[20]       = (float(*)[20])(smem_raw);
    float (*vs)[20]       = (float(*)[20])(smem_raw + 10240);
    float (*part)[16][17] = (float(*)[16][17])(smem_raw + 20480);
    float (*wos)[20]      = (float(*)[20])(smem_raw);            // phase2 overlay
    __shared__ float Ms[16][16];

    const int bh = blockIdx.x, b = bh >> 4, h = bh & 15;
    const float* __restrict__ q = g_xq + (size_t)b*S_*D_ + h*16;
    const float* __restrict__ v = g_xv + (size_t)b*S_*D_ + h*16;
    const int t = threadIdx.x;
    const int grp = t >> 4, lt = t & 15;
    const int e4 = (lt >> 2) * 4, f4 = (lt & 3) * 4;
    float c[4][4] = {};

    for (int chunk = 0; chunk < 8; chunk++) {
        int sb = chunk * 128;
        #pragma unroll
        for (int i = 0; i < 2; i++) {
            int idx = t + i*256;
            int row = idx >> 2, c4 = (idx & 3) * 4;
            *(float4*)&qs[row][c4] = *(const float4*)(q + (size_t)(sb+row)*D_ + c4);
            *(float4*)&vs[row][c4] = *(const float4*)(v + (size_t)(sb+row)*D_ + c4);
        }
        __syncthreads();
        int r0 = grp * 8;
        #pragma unroll
        for (int ss = 0; ss < 8; ss++) {
            float4 q4 = *(const float4*)&qs[r0+ss][e4];
            float4 v4 = *(const float4*)&vs[r0+ss][f4];
            c[0][0] += q4.x*v4.x; c[0][1] += q4.x*v4.y; c[0][2] += q4.x*v4.z; c[0][3] += q4.x*v4.w;
            c[1][0] += q4.y*v4.x; c[1][1] += q4.y*v4.y; c[1][2] += q4.y*v4.z; c[1][3] += q4.y*v4.w;
            c[2][0] += q4.z*v4.x; c[2][1] += q4.z*v4.y; c[2][2] += q4.z*v4.z; c[2][3] += q4.z*v4.w;
            c[3][0] += q4.w*v4.x; c[3][1] += q4.w*v4.y; c[3][2] += q4.w*v4.z; c[3][3] += q4.w*v4.w;
        }
        __syncthreads();
    }
    #pragma unroll
    for (int i = 0; i < 4; i++)
        #pragma unroll
        for (int j = 0; j < 4; j++)
            part[grp][e4+i][f4+j] = c[i][j];
    __syncthreads();
    {
        int e = t >> 4, f = t & 15;
        float s = 0.f;
        #pragma unroll
        for (int gg = 0; gg < 16; gg++) s += part[gg][e][f];
        __syncthreads();                 // all part reads done before wos overwrite
        Ms[e][f] = s * 0.25f;            // 1/sqrt(HD=16)
    }
    #pragma unroll
    for (int i = 0; i < 4; i++) {
        int idx = t + i*256;
        int row = idx >> 2, c4 = (idx & 3) * 4;
        *(float4*)&wos[row][c4] = *(const float4*)(Wo + (size_t)row*D_ + h*16 + c4);
    }
    __syncthreads();
    const int n = t;
    float vals[16];
    #pragma unroll
    for (int e = 0; e < 16; e++) {
        float a = 0.f;
        #pragma unroll
        for (int f = 0; f < 16; f++) a += Ms[e][f] * wos[n][f];
        vals[e] = a;
    }
    size_t obase = ((size_t)b*D_ + n)*128 + h*8;   // unsigned (pair) index
    #pragma unroll
    for (int e = 0; e < 16; e += 2) {
        uint2 pr = splt2(vals[e], vals[e+1]);
        g_w2h[obase + e/2] = pr.x;
        g_w2l[obase + e/2] = pr.y;
    }
}

// ---------------------------------------------------------------------------
// K3: out_b = xq_b @ W2T_b^T + bo. BM=128 BN=64 BK=16, 256 threads,
// 8 warps (4m x 2n), warp tile 32x32. grid (4, 8, 8).
// ---------------------------------------------------------------------------
__global__ __launch_bounds__(256, 2) void out_tc(
    const float* __restrict__ bo, float* __restrict__ out)
{
    extern __shared__ __align__(16) char dyn2[];
    const unsigned smb = s2u(dyn2);
    const int t = threadIdx.x;
    const int lane = t & 31, warp = t >> 5;
    const int g = lane >> 2, tg = lane & 3;
    const int wm = warp & 3, wn = warp >> 2;
    const unsigned lofs = (unsigned)((lane & 15)*RP + (lane >> 4)*16);
    const int bz = blockIdx.z;
    const int m0 = blockIdx.y * 128, n0 = blockIdx.x * 64;
    const int ra0 = bz*S_ + m0;             // global A row base
    const int rb0 = bz*D_ + n0;             // global B row base

    float acc[2][4][4] = {};

    #define OUT_ISSUE(s_, kt_) do {                                             \
        unsigned sb_ = smb + (s_)*OSTG;                                         \
        int kbase = (kt_)*8;                                                    \
        _Pragma("unroll")                                                       \
        for (int i = 0; i < 2; i++) {                                           \
            int id = t + i*256;                                                 \
            int row = id >> 2, rem = id & 3;                                    \
            int pl = rem >> 1, ch = rem & 1;                                    \
            const unsigned* sA = pl ? g_xql : g_xqh;                            \
            cpa16s(sb_ + (unsigned)(pl*6144 + row*RP + ch*16),                  \
                   sA + (size_t)(ra0+row)*128 + kbase + ch*4);                  \
        }                                                                       \
        {                                                                       \
            int row = t >> 2, rem = t & 3;                                      \
            int pl = rem >> 1, ch = rem & 1;                                    \
            const unsigned* sB = pl ? g_w2l : g_w2h;                            \
            cpa16s(sb_ + OBH + (unsigned)(pl*3072 + row*RP + ch*16),            \
                   sB + (size_t)(rb0+row)*128 + kbase + ch*4);                  \
        }                                                                       \
        CP_COMMIT();                                                            \
    } while (0)

    OUT_ISSUE(0, 0);
    OUT_ISSUE(1, 1);

    #pragma unroll
    for (int it = 0; it < 16; it++) {
        const int cur = it % 3;
        if (it < 15) { CP_WAIT1(); } else { CP_WAIT0(); }
        __syncthreads();
        if (it + 2 < 16) { OUT_ISSUE((it+2)%3, it+2); }
        {
            unsigned sb = smb + cur*OSTG;
            unsigned aH[2][4], aL[2][4], bH[4][2], bL[4][2];
            LOAD_A(sb + OAH, sb + OAL);
            LOAD_B32(bH, sb + OBH);
            LOAD_B32(bL, sb + OBL);
            MMA_3TERM(acc);
        }
    }
    #undef OUT_ISSUE

    #pragma unroll
    for (int mi = 0; mi < 2; mi++) {
        #pragma unroll
        for (int half = 0; half < 2; half++) {
            int r = bz*S_ + m0 + wm*32 + mi*16 + g + half*8;
            #pragma unroll
            for (int ni = 0; ni < 4; ni++) {
                int d = n0 + wn*32 + ni*8 + 2*tg;
                float2 o = make_float2(acc[mi][ni][half*2+0] + bo[d],
                                       acc[mi][ni][half*2+1] + bo[d+1]);
                *(float2*)(out + (size_t)r*D_ + d) = o;
            }
        }
    }
}

// ---------------------------------------------------------------------------
extern "C" void kernel_launch(void* const* d_in, const int* in_sizes, int n_in,
                              void* d_out, int out_size)
{
    (void)in_sizes; (void)n_in; (void)out_size;
    const float* x   = (const float*)d_in[0];
    const float* wqw = (const float*)d_in[1];
    const float* wqb = (const float*)d_in[2];
    // d_in[3], d_in[4] = wk_w, wk_b : dead in reference
    const float* wvw = (const float*)d_in[5];
    const float* wvb = (const float*)d_in[6];
    const float* wow = (const float*)d_in[7];
    const float* wob = (const float*)d_in[8];
    float* out = (float*)d_out;

    cudaFuncSetAttribute(qv2_tc, cudaFuncAttributeMaxDynamicSharedMemorySize, QV_SMEM);
    cudaFuncSetAttribute(out_tc, cudaFuncAttributeMaxDynamicSharedMemorySize, OUT_SMEM);

    presplit_kernel<<<544, 256>>>(x, wqw, wvw);
    qv2_tc<<<dim3(64, 4), 256, QV_SMEM>>>(wqb, wvb);
    mw_kernel<<<128, 256>>>(wow);
    out_tc<<<dim3(4, 8, 8), 256, OUT_SMEM>>>(wob, out);
}